// round 4
// baseline (speedup 1.0000x reference)
#include <cuda_runtime.h>
#include <math.h>

// SpectralConv2d: B=8, C=64, H=W=256, modes 16x16.
// Dense partial-DFT stages; FFMA2 (f32x2) with mov-free u64 operand loads.

#define NIMG 512              // B*C images of 256x256

typedef unsigned long long u64;

__device__ __forceinline__ u64 pk2(float lo, float hi) {
    u64 r; asm("mov.b64 %0,{%1,%2};" : "=l"(r) : "f"(lo), "f"(hi)); return r;
}
__device__ __forceinline__ float2 upk2(u64 v) {
    float2 r; asm("mov.b64 {%0,%1},%2;" : "=f"(r.x), "=f"(r.y) : "l"(v)); return r;
}
__device__ __forceinline__ void fma2(u64 &d, u64 a, u64 b) {
    asm("fma.rn.f32x2 %0,%1,%2,%0;" : "+l"(d) : "l"(a), "l"(b));
}
__device__ __forceinline__ float hsum(u64 v) { float2 f = upk2(v); return f.x + f.y; }

// tables: angle a = 2*pi/256
__device__ u64   g_tab[256 * 16];    // [t][k] packed (cos akt, sin akt)
__device__ float g_tabC[16 * 256];   // [k][t] cos
__device__ float g_tabS[16 * 256];   // [k][t] sin
// X_ft corner per (b,i): [img][k*16+w], complex
__device__ float2 g_X[NIMG * 256];
// Z transposed: [img][j][p], j<16: cos-coeff row j, j>=16: sin-coeff row j-16
__device__ float  g_Z[(size_t)NIMG * 32 * 256];

// ---------------- table init ------------------------------------------------
__global__ void k_init() {
    int i = blockIdx.x * blockDim.x + threadIdx.x;
    if (i >= 4096) return;
    int t = i >> 4, k = i & 15;
    int m = (t * k) & 255;
    double s, c;
    sincospi((double)m / 128.0, &s, &c);
    g_tab[i] = pk2((float)c, (float)s);
    g_tabC[k * 256 + t] = (float)c;
    g_tabS[k * 256 + t] = (float)s;
}

// ---------------- K1: x -> A (partial DFT over H) -> corner DFT over W ------
__global__ void __launch_bounds__(256) k1(const float* __restrict__ x) {
    extern __shared__ __align__(16) char smem_raw[];
    u64*   s_tab = (u64*)smem_raw;                 // [t][16] packed, 32KB
    float* s_tc  = (float*)smem_raw;               // phase2: [w][x] cos, 16KB
    float* s_ts  = (float*)(smem_raw + 16384);     // phase2: [w][x] sin, 16KB
    float* s_Ar  = (float*)(smem_raw + 32768);     // [k][x] 16KB
    float* s_As  = (float*)(smem_raw + 49152);     // [k][x] 16KB
    int img = blockIdx.x, tid = threadIdx.x;

    for (int i = tid; i < 4096; i += 256) s_tab[i] = g_tab[i];
    __syncthreads();

    // Phase 1: A[k,x] over h. acc = (sum v*cos, sum v*sin)
    const float* xp = x + (size_t)img * 65536 + tid;
    u64 acc[16];
#pragma unroll
    for (int k = 0; k < 16; k++) acc[k] = 0ull;

#pragma unroll 4
    for (int h = 0; h < 256; h++) {
        float v = xp[(size_t)h * 256];             // coalesced LDG
        u64 vv = pk2(v, v);
        const ulonglong2* t2 = (const ulonglong2*)(s_tab + h * 16);
#pragma unroll
        for (int k2 = 0; k2 < 8; k2++) {
            ulonglong2 q = t2[k2];                 // LDS.128 -> two u64, no movs
            fma2(acc[2 * k2],     vv, q.x);
            fma2(acc[2 * k2 + 1], vv, q.y);
        }
    }
#pragma unroll
    for (int k = 0; k < 16; k++) {
        float2 f = upk2(acc[k]);
        s_Ar[k * 256 + tid] = f.x;                 // ar
        s_As[k * 256 + tid] = f.y;                 // as (A = ar - i*as)
    }
    __syncthreads();

    // swap table region to [w][x] cos/sin planes
    for (int i = tid; i < 4096; i += 256) {
        s_tc[i] = g_tabC[i];
        s_ts[i] = g_tabS[i];
    }
    __syncthreads();

    // Phase 2: X[k,w] = sum_x (ar - i as)(cos - i sin)
    int k = tid >> 4, w = tid & 15;
    const u64* ar2 = (const u64*)(s_Ar + k * 256);
    const u64* as2 = (const u64*)(s_As + k * 256);
    const u64* c2  = (const u64*)(s_tc + w * 256);
    const u64* s2  = (const u64*)(s_ts + w * 256);
    u64 XR1 = 0ull, XR2 = 0ull, XI1 = 0ull, XI2 = 0ull;
#pragma unroll 4
    for (int xx = 0; xx < 128; xx++) {
        u64 a = ar2[xx], b = as2[xx], c = c2[xx], s = s2[xx];
        fma2(XR1, a, c);   // ar*cos
        fma2(XR2, b, s);   // as*sin
        fma2(XI1, b, c);   // as*cos
        fma2(XI2, a, s);   // ar*sin
    }
    float xr = hsum(XR1) - hsum(XR2);
    float xi = -(hsum(XI1) + hsum(XI2));
    g_X[img * 256 + tid] = make_float2(xr, xi);
}

// ---------------- K2 (fused): channel mix + inverse-k DFT -> Z (transposed) -
__global__ void __launch_bounds__(256) k2(const float* __restrict__ wre,
                                          const float* __restrict__ wim) {
    __shared__ float2 sG[256];
    int b = blockIdx.x >> 6, o = blockIdx.x & 63, tid = threadIdx.x;

    // Phase A: G[k,w] = sum_i X[b,i,k,w] * (wr + i wi);  tid = k*16+w
    {
        const float2* Xb = g_X + b * 64 * 256;
        float gr = 0.f, gi = 0.f;
#pragma unroll 4
        for (int i = 0; i < 64; i++) {
            float2 xv = Xb[i * 256 + tid];
            float wr = wre[(size_t)(i * 64 + o) * 256 + tid];
            float wi = wim[(size_t)(i * 64 + o) * 256 + tid];
            gr = fmaf(xv.x, wr, fmaf(-xv.y, wi, gr));
            gi = fmaf(xv.x, wi, fmaf( xv.y, wr, gi));
        }
        sG[tid] = make_float2(gr, gi);
    }
    __syncthreads();

    // Phase B: Y[p,w] = sum_k G[k,w] e^{+i a k p};  tid = p
    int p = tid;
    float2 tp[16];
#pragma unroll
    for (int k = 0; k < 16; k++)
        tp[k] = make_float2(g_tabC[k * 256 + p], g_tabS[k * 256 + p]);  // coalesced

    float zc[16], zs[16];
#pragma unroll
    for (int w = 0; w < 16; w++) {
        float yr = 0.f, yi = 0.f;
#pragma unroll
        for (int k = 0; k < 16; k++) {
            float2 g = sG[k * 16 + w];             // broadcast
            yr += g.x * tp[k].x - g.y * tp[k].y;
            yi += g.x * tp[k].y + g.y * tp[k].x;
        }
        zc[w] = yr; zs[w] = -yi;
    }
    const float s1 = 1.0f / 65536.0f, s2 = 2.0f / 65536.0f;
    zc[0] *= s1; zs[0] = 0.f;
#pragma unroll
    for (int w = 1; w < 16; w++) { zc[w] *= s2; zs[w] *= s2; }

    // transposed store: g_Z[img][j][p], coalesced over p
    float* zb = g_Z + (size_t)blockIdx.x * 32 * 256 + p;
#pragma unroll
    for (int j = 0; j < 16; j++) {
        zb[j * 256]        = zc[j];
        zb[(16 + j) * 256] = zs[j];
    }
}

// ---------------- K3: out = Z^T(p,j) @ B(j,q), register-tiled GEMM ----------
// Block = one 64p x 256q tile of one image. Thread = 8p x 8q micro-tile.
// K=32 (j). Z rows broadcast, basis LDS.128 conflict-free, 32 indep acc chains.
__global__ void __launch_bounds__(256) k3(float* __restrict__ out) {
    extern __shared__ __align__(16) char smem_raw[];
    float* s_B  = (float*)smem_raw;            // [32][256] basis, 32KB
    float* s_zT = (float*)(smem_raw + 32768);  // [32][64] z tile, 8KB
    int img = blockIdx.x >> 2, pt = blockIdx.x & 3, tid = threadIdx.x;

    for (int i = tid; i < 4096; i += 256) {
        s_B[i]        = g_tabC[i];             // rows 0..15: cos
        s_B[4096 + i] = g_tabS[i];             // rows 16..31: sin
    }
    {
        const float* zsrc = g_Z + (size_t)img * 8192 + pt * 64;
        for (int i = tid; i < 2048; i += 256) {
            int j = i >> 6, pp = i & 63;
            s_zT[j * 64 + pp] = zsrc[j * 256 + pp];
        }
    }
    __syncthreads();

    int tx = tid & 31, ty = tid >> 5;          // tx: q-octet, ty: p-octet (warp)
    int qb = tx * 8;

    u64 acc[8][4];
#pragma unroll
    for (int pi = 0; pi < 8; pi++)
#pragma unroll
        for (int qp = 0; qp < 4; qp++) acc[pi][qp] = 0ull;

#pragma unroll 4
    for (int j = 0; j < 32; j++) {
        const float4* zr = (const float4*)(s_zT + j * 64 + ty * 8);  // broadcast
        float4 za = zr[0], zb4 = zr[1];
        u64 zd[8];
        zd[0] = pk2(za.x, za.x);  zd[1] = pk2(za.y, za.y);
        zd[2] = pk2(za.z, za.z);  zd[3] = pk2(za.w, za.w);
        zd[4] = pk2(zb4.x, zb4.x); zd[5] = pk2(zb4.y, zb4.y);
        zd[6] = pk2(zb4.z, zb4.z); zd[7] = pk2(zb4.w, zb4.w);
        const ulonglong2* bq = (const ulonglong2*)(s_B + j * 256 + qb);
        ulonglong2 b01 = bq[0], b23 = bq[1];   // 8 basis values as 4 u64
#pragma unroll
        for (int pi = 0; pi < 8; pi++) {
            fma2(acc[pi][0], zd[pi], b01.x);
            fma2(acc[pi][1], zd[pi], b01.y);
            fma2(acc[pi][2], zd[pi], b23.x);
            fma2(acc[pi][3], zd[pi], b23.y);
        }
    }

    float* op = out + (size_t)img * 65536 + (size_t)(pt * 64 + ty * 8) * 256 + qb;
#pragma unroll
    for (int pi = 0; pi < 8; pi++) {
        ulonglong2* o2 = (ulonglong2*)(op + (size_t)pi * 256);
        ulonglong2 v0; v0.x = acc[pi][0]; v0.y = acc[pi][1];
        ulonglong2 v1; v1.x = acc[pi][2]; v1.y = acc[pi][3];
        o2[0] = v0;                            // STG.128
        o2[1] = v1;
    }
}

extern "C" void kernel_launch(void* const* d_in, const int* in_sizes, int n_in,
                              void* d_out, int out_size) {
    const float* x   = (const float*)d_in[0];
    const float* wre = (const float*)d_in[1];
    const float* wim = (const float*)d_in[2];
    float* out = (float*)d_out;

    cudaFuncSetAttribute(k1, cudaFuncAttributeMaxDynamicSharedMemorySize, 65536);
    cudaFuncSetAttribute(k3, cudaFuncAttributeMaxDynamicSharedMemorySize, 40960);

    k_init<<<16, 256>>>();
    k1 <<<NIMG, 256, 65536>>>(x);
    k2 <<<NIMG, 256>>>(wre, wim);
    k3 <<<NIMG * 4, 256, 40960>>>(out);
}

// round 7
// speedup vs baseline: 1.7925x; 1.7925x over previous
#include <cuda_runtime.h>
#include <math.h>

// SpectralConv2d: B=8, C=64, H=W=256, modes 16x16.
// Dense partial-DFT stages with reflection-symmetry folding (4x FMA reduction
// on the two big stages) -> both become HBM-bound. All scalar fp32.

#define NIMG 512              // B*C images of 256x256

// tables (angle a = 2*pi/256)
__device__ float2 g_tab[256 * 16];   // [t][k] (cos akt, sin akt)
__device__ float  g_tabC[16 * 256];  // [k][t] cos
__device__ float  g_tabS[16 * 256];  // [k][t] sin
// k1 phase-1 folded table: [h][32] for h=0..63:
//   [0..7]  cos(a*(2m)*h)   [8..15] cos(a*(2m+1)*h)
//   [16..23] sin(a*(2m)*h)  [24..31] sin(a*(2m+1)*h)
__device__ float  g_tab1[64 * 32];
// X_ft corner per (b,i): [img][k*16+w], complex
__device__ float2 g_X[NIMG * 256];
// Z per (b,o): [img][p][j], j<16: cos-coeff, j>=16: sin-coeff
__device__ float  g_Z[(size_t)NIMG * 256 * 32];

// ---------------- table init ------------------------------------------------
__global__ void k_init() {
    int i = blockIdx.x * blockDim.x + threadIdx.x;
    if (i < 4096) {
        int t = i >> 4, k = i & 15;
        int m = (t * k) & 255;
        double s, c;
        sincospi((double)m / 128.0, &s, &c);       // angle = 2*pi*m/256
        g_tab[i] = make_float2((float)c, (float)s);
        g_tabC[k * 256 + t] = (float)c;
        g_tabS[k * 256 + t] = (float)s;
    }
    if (i < 2048) {
        int h = i >> 5, j = i & 31;
        int m = j & 7;
        int k = ((j & 15) < 8) ? (2 * m) : (2 * m + 1);
        int mm = (h * k) & 255;
        double s, c;
        sincospi((double)mm / 128.0, &s, &c);
        g_tab1[i] = (j < 16) ? (float)c : (float)s;
    }
}

// ---------------- K1: x -> A (folded partial DFT over H) -> corner W DFT ----
// Block = image, thread = x column.
__global__ void __launch_bounds__(256) k1(const float* __restrict__ x) {
    extern __shared__ __align__(16) char smem_raw[];
    float*  s_t1  = (float*)smem_raw;                   // [64][32]  8KB
    float2* s_tab = (float2*)(smem_raw + 8192);         // [t][16]  32KB
    float2* s_A   = (float2*)(smem_raw + 8192 + 32768); // [k][x]   32KB
    int img = blockIdx.x, tid = threadIdx.x;

    for (int i = tid; i < 2048; i += 256) s_t1[i] = g_tab1[i];
    for (int i = tid; i < 4096; i += 256) s_tab[i] = g_tab[i];
    __syncthreads();

    // Phase 1: ar[k] = sum_h x[h]cos(akh), as[k] = sum_h x[h]sin(akh)
    const float* xp = x + (size_t)img * 65536 + tid;
    float x0   = xp[0];
    float x64v = xp[64 * 256];
    float x128 = xp[128 * 256];
    float x192 = xp[192 * 256];

    float arE[8], arO[8], asE[8], asO[8];
#pragma unroll
    for (int m = 0; m < 8; m++) { arE[m] = 0.f; arO[m] = 0.f; asE[m] = 0.f; asO[m] = 0.f; }

#pragma unroll 2
    for (int h = 1; h < 64; h++) {
        float a1 = xp[(size_t)h * 256];
        float a2 = xp[(size_t)(256 - h) * 256];
        float a3 = xp[(size_t)(128 - h) * 256];
        float a4 = xp[(size_t)(128 + h) * 256];
        float u1 = a1 + a2, v1 = a1 - a2;
        float u2 = a3 + a4, v2 = a3 - a4;
        float uE = u1 + u2, uO = u1 - u2;
        float vE = v1 - v2, vO = v1 + v2;
        const float4* t4 = (const float4*)(s_t1 + h * 32);   // broadcast LDS.128
        float4 cE0 = t4[0], cE1 = t4[1], cO0 = t4[2], cO1 = t4[3];
        float4 sE0 = t4[4], sE1 = t4[5], sO0 = t4[6], sO1 = t4[7];
        arE[0] = fmaf(uE, cE0.x, arE[0]); arE[1] = fmaf(uE, cE0.y, arE[1]);
        arE[2] = fmaf(uE, cE0.z, arE[2]); arE[3] = fmaf(uE, cE0.w, arE[3]);
        arE[4] = fmaf(uE, cE1.x, arE[4]); arE[5] = fmaf(uE, cE1.y, arE[5]);
        arE[6] = fmaf(uE, cE1.z, arE[6]); arE[7] = fmaf(uE, cE1.w, arE[7]);
        arO[0] = fmaf(uO, cO0.x, arO[0]); arO[1] = fmaf(uO, cO0.y, arO[1]);
        arO[2] = fmaf(uO, cO0.z, arO[2]); arO[3] = fmaf(uO, cO0.w, arO[3]);
        arO[4] = fmaf(uO, cO1.x, arO[4]); arO[5] = fmaf(uO, cO1.y, arO[5]);
        arO[6] = fmaf(uO, cO1.z, arO[6]); arO[7] = fmaf(uO, cO1.w, arO[7]);
        asE[0] = fmaf(vE, sE0.x, asE[0]); asE[1] = fmaf(vE, sE0.y, asE[1]);
        asE[2] = fmaf(vE, sE0.z, asE[2]); asE[3] = fmaf(vE, sE0.w, asE[3]);
        asE[4] = fmaf(vE, sE1.x, asE[4]); asE[5] = fmaf(vE, sE1.y, asE[5]);
        asE[6] = fmaf(vE, sE1.z, asE[6]); asE[7] = fmaf(vE, sE1.w, asE[7]);
        asO[0] = fmaf(vO, sO0.x, asO[0]); asO[1] = fmaf(vO, sO0.y, asO[1]);
        asO[2] = fmaf(vO, sO0.z, asO[2]); asO[3] = fmaf(vO, sO0.w, asO[3]);
        asO[4] = fmaf(vO, sO1.x, asO[4]); asO[5] = fmaf(vO, sO1.y, asO[5]);
        asO[6] = fmaf(vO, sO1.z, asO[6]); asO[7] = fmaf(vO, sO1.w, asO[7]);
    }

    // boundary terms: h=0,64,128,192
    float u64v = x64v + x192, v64v = x64v - x192;
    float sgn = 1.f;
#pragma unroll
    for (int m = 0; m < 8; m++) {
        // k = 2m : ar = x0 + x128 + arE + (-1)^m*u64 ; as = asE
        s_A[(2 * m) * 256 + tid]     = make_float2(x0 + x128 + arE[m] + sgn * u64v, asE[m]);
        // k = 2m+1: ar = x0 - x128 + arO ; as = asO + (-1)^m*v64
        s_A[(2 * m + 1) * 256 + tid] = make_float2(x0 - x128 + arO[m], asO[m] + sgn * v64v);
        sgn = -sgn;
    }
    __syncthreads();

    // Phase 2: X[k,w] = sum_x (ar - i*as)(cos - i sin)
    int k = tid >> 4, w = tid & 15;
    float xr = 0.f, xi = 0.f;
#pragma unroll 4
    for (int xx = 0; xx < 256; xx++) {
        float2 a  = s_A[k * 256 + xx];     // broadcast (same addr per 16 lanes)
        float2 cs = s_tab[xx * 16 + w];
        xr += a.x * cs.x - a.y * cs.y;
        xi -= a.y * cs.x + a.x * cs.y;
    }
    g_X[img * 256 + tid] = make_float2(xr, xi);
}

// ---------------- K2 (fused): channel mix + inverse-k DFT -> Z --------------
__global__ void __launch_bounds__(256) k2(const float* __restrict__ wre,
                                          const float* __restrict__ wim) {
    __shared__ float2 sG[256];
    int b = blockIdx.x >> 6, o = blockIdx.x & 63, tid = threadIdx.x;

    // Phase A: G[k,w] = sum_i X[b,i,k,w] * (wr + i wi);  tid = k*16+w
    {
        const float2* Xb = g_X + b * 64 * 256;
        float gr = 0.f, gi = 0.f;
#pragma unroll 4
        for (int i = 0; i < 64; i++) {
            float2 xv = Xb[i * 256 + tid];
            float wr = wre[(size_t)(i * 64 + o) * 256 + tid];
            float wi = wim[(size_t)(i * 64 + o) * 256 + tid];
            gr = fmaf(xv.x, wr, fmaf(-xv.y, wi, gr));
            gi = fmaf(xv.x, wi, fmaf( xv.y, wr, gi));
        }
        sG[tid] = make_float2(gr, gi);
    }
    __syncthreads();

    // Phase B: Y[p,w] = sum_k G[k,w] e^{+i a k p};  tid = p
    int p = tid;
    float2 tp[16];
#pragma unroll
    for (int k = 0; k < 16; k++)
        tp[k] = make_float2(g_tabC[k * 256 + p], g_tabS[k * 256 + p]);  // coalesced

    float zc[16], zs[16];
#pragma unroll
    for (int w = 0; w < 16; w++) {
        float yr = 0.f, yi = 0.f;
#pragma unroll
        for (int k = 0; k < 16; k++) {
            float2 g = sG[k * 16 + w];
            yr += g.x * tp[k].x - g.y * tp[k].y;
            yi += g.x * tp[k].y + g.y * tp[k].x;
        }
        zc[w] = yr; zs[w] = -yi;
    }
    const float s1 = 1.0f / 65536.0f, s2 = 2.0f / 65536.0f;
    zc[0] *= s1; zs[0] = 0.f;
#pragma unroll
    for (int w = 1; w < 16; w++) { zc[w] *= s2; zs[w] *= s2; }

    float4* z4 = (float4*)(g_Z + ((size_t)blockIdx.x * 256 + p) * 32);
    z4[0] = make_float4(zc[0],  zc[1],  zc[2],  zc[3]);
    z4[1] = make_float4(zc[4],  zc[5],  zc[6],  zc[7]);
    z4[2] = make_float4(zc[8],  zc[9],  zc[10], zc[11]);
    z4[3] = make_float4(zc[12], zc[13], zc[14], zc[15]);
    z4[4] = make_float4(zs[0],  zs[1],  zs[2],  zs[3]);
    z4[5] = make_float4(zs[4],  zs[5],  zs[6],  zs[7]);
    z4[6] = make_float4(zs[8],  zs[9],  zs[10], zs[11]);
    z4[7] = make_float4(zs[12], zs[13], zs[14], zs[15]);
}

// ---------------- K3: folded inverse W transform ----------------------------
// out[p,q] = sum_w Zc[p,w]cos(awq) + Zs[p,w]sin(awq)
// Thread qs in 1..63 computes Ce,Co,Se,So once -> 4 outputs (q, 256-q, 128-q, 128+q).
// Thread qs==0 handles q in {0,64,128,192}.
__global__ void __launch_bounds__(256) k3(float* __restrict__ out) {
    __shared__ __align__(16) float s_z[256 * 32];   // [p][32] 32KB
    int img = blockIdx.x, tid = threadIdx.x;
    {
        const float4* zsrc = (const float4*)(g_Z + (size_t)img * 8192);
        float4* zdst = (float4*)s_z;
        for (int i = tid; i < 2048; i += 256) zdst[i] = zsrc[i];
    }
    __syncthreads();

    int qs = tid & 63, pg = tid >> 6;               // 4 p-groups of 64 rows
    float* ob = out + (size_t)img * 65536;

    if (qs == 0) {
        for (int pi = 0; pi < 64; pi++) {
            int p = pg * 64 + pi;
            const float* z = s_z + p * 32;
            float o0 = 0.f, o128 = 0.f, c64 = 0.f, s64 = 0.f;
#pragma unroll
            for (int w = 0; w < 16; w++) {
                float v = z[w];
                o0 += v;
                o128 += (w & 1) ? -v : v;
            }
            // q=64: cos(w*pi/2): +1 @ w=4m, -1 @ w=4m+2; sin(w*pi/2): +1 @ 4m+1, -1 @ 4m+3
#pragma unroll
            for (int m = 0; m < 4; m++) {
                c64 += z[4 * m]          - z[4 * m + 2];
                s64 += z[16 + 4 * m + 1] - z[16 + 4 * m + 3];
            }
            float* op = ob + (size_t)p * 256;
            op[0]   = o0;
            op[128] = o128;
            op[64]  = c64 + s64;
            op[192] = c64 - s64;
        }
    } else {
        float c[16], s[16];
#pragma unroll
        for (int w = 0; w < 16; w++) {
            float2 cs = g_tab[qs * 16 + w];
            c[w] = cs.x; s[w] = cs.y;
        }
        for (int pi = 0; pi < 64; pi++) {
            int p = pg * 64 + pi;
            const float4* z4 = (const float4*)(s_z + p * 32);  // broadcast LDS.128
            float z[32];
#pragma unroll
            for (int t = 0; t < 8; t++) {
                float4 v = z4[t];
                z[4 * t] = v.x; z[4 * t + 1] = v.y; z[4 * t + 2] = v.z; z[4 * t + 3] = v.w;
            }
            float Ce = 0.f, Co = 0.f, Se = 0.f, So = 0.f;
#pragma unroll
            for (int m = 0; m < 8; m++) {
                Ce = fmaf(z[2 * m],          c[2 * m],     Ce);
                Co = fmaf(z[2 * m + 1],      c[2 * m + 1], Co);
                Se = fmaf(z[16 + 2 * m],     s[2 * m],     Se);
                So = fmaf(z[16 + 2 * m + 1], s[2 * m + 1], So);
            }
            float t1 = Ce + Co, t2 = Se + So;
            float t3 = Ce - Co, t4 = So - Se;
            float* op = ob + (size_t)p * 256;
            op[qs]        = t1 + t2;
            op[256 - qs]  = t1 - t2;
            op[128 - qs]  = t3 + t4;
            op[128 + qs]  = t3 - t4;
        }
    }
}

extern "C" void kernel_launch(void* const* d_in, const int* in_sizes, int n_in,
                              void* d_out, int out_size) {
    const float* x   = (const float*)d_in[0];
    const float* wre = (const float*)d_in[1];
    const float* wim = (const float*)d_in[2];
    float* out = (float*)d_out;

    cudaFuncSetAttribute(k1, cudaFuncAttributeMaxDynamicSharedMemorySize, 73728);

    k_init<<<16, 256>>>();
    k1 <<<NIMG, 256, 73728>>>(x);
    k2 <<<NIMG, 256>>>(wre, wim);
    k3 <<<NIMG, 256>>>(out);
}